// round 2
// baseline (speedup 1.0000x reference)
#include <cuda_runtime.h>

#define LL 1024
#define BB 4
#define NHID 128
#define NH 10
#define HD 10
#define DD 100
#define INV_SQRT_HD 0.31622776601683794f

// Scratch (device globals: no allocation allowed)
static __device__ float q_s[BB][DD][LL];        // q = WQ @ x   (also k/v)
static __device__ float E_s[BB][NH][LL];        // exp(s_j - gmax)
static __device__ float W_s[BB][NH][HD][LL];    // E * k  (d-major for coalesced smem fill)
// att in the reference's scrambled channel layout:
// att_flat[b][n*LL*HD + i*HD + d] = att[b,n,i,d]; read by k4 as [DD][LL] row-major.
static __device__ float att_s[BB][DD * LL];

// ---------------------------------------------------------------------------
// Kernel 1: q[b,c,l] = sum_h wq_w[c,h] * x[b,h,l] + wq_b[c]
// grid (32 l-tiles, B), 128 threads. Register-blocked: thread owns 25 c's, 1 l.
// ---------------------------------------------------------------------------
__global__ void __launch_bounds__(128) k1_q(const float* __restrict__ x,
                                            const float* __restrict__ wq_w,
                                            const float* __restrict__ wq_b) {
    int b = blockIdx.y, lt = blockIdx.x;
    int tid = threadIdx.x, tc = tid >> 5, tl = tid & 31;
    int l = lt * 32 + tl;

    __shared__ float xs[16][33];
    __shared__ float ws[DD][16];

    float acc[25];
#pragma unroll
    for (int i = 0; i < 25; i++) acc[i] = 0.f;

    for (int hc = 0; hc < NHID; hc += 16) {
        for (int idx = tid; idx < 16 * 32; idx += 128) {
            int h = idx >> 5, ll = idx & 31;
            xs[h][ll] = x[((b * NHID + hc + h) * LL) + lt * 32 + ll];
        }
        for (int idx = tid; idx < DD * 16; idx += 128) {
            int c = idx >> 4, h = idx & 15;
            ws[c][h] = wq_w[c * NHID + hc + h];
        }
        __syncthreads();
#pragma unroll
        for (int h = 0; h < 16; h++) {
            float xv = xs[h][tl];
#pragma unroll
            for (int i = 0; i < 25; i++) acc[i] += ws[tc + 4 * i][h] * xv;
        }
        __syncthreads();
    }
#pragma unroll
    for (int i = 0; i < 25; i++) {
        int c = tc + 4 * i;
        q_s[b][c][l] = acc[i] + __ldg(&wq_b[c]);
    }
}

// ---------------------------------------------------------------------------
// Kernel 2: per (b,n): t[l] = inv_sqrt * sum_d q[n*hd+d][l]*wedge_w[hd+d];
// gmax = max_l t; E = exp(t-gmax); W[d][l] = E * q_d.
// grid (NH, B), 1024 threads (thread = l).
// ---------------------------------------------------------------------------
__global__ void __launch_bounds__(1024) k2_ew(const float* __restrict__ wedge_w) {
    int b = blockIdx.y, n = blockIdx.x;
    int l = threadIdx.x;

    float qd[HD];
    float t = 0.f;
#pragma unroll
    for (int d = 0; d < HD; d++) {
        qd[d] = q_s[b][n * HD + d][l];
        t += qd[d] * __ldg(&wedge_w[HD + d]);
    }
    t *= INV_SQRT_HD;

    __shared__ float red[32];
    float m = t;
#pragma unroll
    for (int o = 16; o; o >>= 1) m = fmaxf(m, __shfl_xor_sync(0xffffffffu, m, o));
    if ((l & 31) == 0) red[l >> 5] = m;
    __syncthreads();
    if (l < 32) {
        float mm = red[l];
#pragma unroll
        for (int o = 16; o; o >>= 1) mm = fmaxf(mm, __shfl_xor_sync(0xffffffffu, mm, o));
        if (l == 0) red[0] = mm;
    }
    __syncthreads();
    float gmax = red[0];

    float E = expf(t - gmax);
    E_s[b][n][l] = E;
#pragma unroll
    for (int d = 0; d < HD; d++) W_s[b][n][d][l] = E * qd[d];
}

// ---------------------------------------------------------------------------
// Kernel 3 (the big one): per (b,n,64-row tile):
//   smem: E[1024] (4KB) + W[10][1024] (40KB).
//   Per row i (one warp per row): pass 1 reads mask (int4), accumulates
//   denom = sum mask*E and acc_d = sum mask*W_d; mask packed into a 32-bit
//   register bitmask. Pass 2 writes alpha = mask*E/denom as float4 streams.
//   Writes att in the reference's scrambled reshape layout.
// grid (NH fastest for L2 mask reuse, 16 tiles, B), 256 threads.
// ---------------------------------------------------------------------------
__global__ void __launch_bounds__(256) k3_attn(const int* __restrict__ edge,
                                               float* __restrict__ alpha_out) {
    int n = blockIdx.x, tile = blockIdx.y, b = blockIdx.z;
    int tid = threadIdx.x;

    __shared__ float E_sm[LL];
    __shared__ float W_sm[HD][LL];

    for (int idx = tid; idx < LL / 4; idx += 256)
        ((float4*)E_sm)[idx] = ((const float4*)&E_s[b][n][0])[idx];
    for (int idx = tid; idx < HD * LL / 4; idx += 256) {
        int d = idx / (LL / 4), r = idx % (LL / 4);
        ((float4*)W_sm[d])[r] = ((const float4*)&W_s[b][n][d][0])[r];
    }
    __syncthreads();

    int warp = tid >> 5, lane = tid & 31;
    const float4* E4 = (const float4*)E_sm;

    for (int r = warp; r < 64; r += 8) {
        int i = tile * 64 + r;
        const int4* mrow = (const int4*)(edge + (size_t)(b * LL + i) * LL);

        float denom = 0.f;
        float acc[HD];
#pragma unroll
        for (int d = 0; d < HD; d++) acc[d] = 0.f;
        unsigned bits = 0u;

#pragma unroll
        for (int it = 0; it < 8; it++) {
            int c4 = it * 32 + lane;
            int4 m = __ldg(&mrow[c4]);
            float f0 = m.x ? 1.f : 0.f, f1 = m.y ? 1.f : 0.f;
            float f2 = m.z ? 1.f : 0.f, f3 = m.w ? 1.f : 0.f;
            bits |= ((m.x ? 1u : 0u) | (m.y ? 2u : 0u) |
                     (m.z ? 4u : 0u) | (m.w ? 8u : 0u)) << (it * 4);
            float4 e = E4[c4];
            denom += f0 * e.x + f1 * e.y + f2 * e.z + f3 * e.w;
#pragma unroll
            for (int d = 0; d < HD; d++) {
                float4 wv = ((const float4*)W_sm[d])[c4];
                acc[d] += f0 * wv.x;
                acc[d] += f1 * wv.y;
                acc[d] += f2 * wv.z;
                acc[d] += f3 * wv.w;
            }
        }

#pragma unroll
        for (int o = 16; o; o >>= 1) denom += __shfl_xor_sync(0xffffffffu, denom, o);
        float inv = 1.0f / denom;

#pragma unroll
        for (int d = 0; d < HD; d++) {
#pragma unroll
            for (int o = 16; o; o >>= 1) acc[d] += __shfl_xor_sync(0xffffffffu, acc[d], o);
        }
        if (lane == 0) {
            // Reference reshape: att[b,n,i,d] -> channel-major flat (n*L*HD + i*HD + d)
            float* arow = &att_s[b][(size_t)n * LL * HD + (size_t)i * HD];
#pragma unroll
            for (int d = 0; d < HD; d++) arow[d] = acc[d] * inv;
        }

        float4* arow4 = (float4*)(alpha_out + (size_t)((b * NH + n) * LL + i) * LL);
#pragma unroll
        for (int it = 0; it < 8; it++) {
            int c4 = it * 32 + lane;
            float4 e = E4[c4];
            unsigned bb = bits >> (it * 4);
            float4 o4;
            o4.x = (bb & 1u) ? e.x * inv : 0.f;
            o4.y = (bb & 2u) ? e.y * inv : 0.f;
            o4.z = (bb & 4u) ? e.z * inv : 0.f;
            o4.w = (bb & 8u) ? e.w * inv : 0.f;
            arow4[c4] = o4;
        }
    }
}

// ---------------------------------------------------------------------------
// Kernel 4: ret[b,o,l] = sum_c wo_w[o,c] * att_flat[b][c*LL + l] + wo_b[o]
// grid (32 l-tiles, B), 128 threads. Thread owns 32 o's, 1 l.
// ---------------------------------------------------------------------------
__global__ void __launch_bounds__(128) k4_out(const float* __restrict__ wo_w,
                                              const float* __restrict__ wo_b,
                                              float* __restrict__ out) {
    int b = blockIdx.y, lt = blockIdx.x;
    int tid = threadIdx.x, tc = tid >> 5, tl = tid & 31;
    int l = lt * 32 + tl;

    __shared__ float as[20][33];
    __shared__ float ws[NHID][20];

    float acc[32];
#pragma unroll
    for (int i = 0; i < 32; i++) acc[i] = 0.f;

    for (int cc = 0; cc < DD; cc += 20) {
        for (int idx = tid; idx < 20 * 32; idx += 128) {
            int c = idx >> 5, ll = idx & 31;
            as[c][ll] = att_s[b][(size_t)(cc + c) * LL + lt * 32 + ll];
        }
        for (int idx = tid; idx < NHID * 20; idx += 128) {
            int o = idx / 20, c = idx % 20;
            ws[o][c] = wo_w[o * DD + cc + c];
        }
        __syncthreads();
#pragma unroll
        for (int c = 0; c < 20; c++) {
            float av = as[c][tl];
#pragma unroll
            for (int i = 0; i < 32; i++) acc[i] += ws[tc + 4 * i][c] * av;
        }
        __syncthreads();
    }
#pragma unroll
    for (int i = 0; i < 32; i++) {
        int o = tc + 4 * i;
        out[((size_t)(b * NHID + o) * LL) + l] = acc[i] + __ldg(&wo_b[o]);
    }
}

// ---------------------------------------------------------------------------
extern "C" void kernel_launch(void* const* d_in, const int* in_sizes, int n_in,
                              void* d_out, int out_size) {
    const float* x       = (const float*)d_in[0];
    const int*   edge    = (const int*)  d_in[1];
    const float* wq_w    = (const float*)d_in[2];
    const float* wq_b    = (const float*)d_in[3];
    const float* wedge_w = (const float*)d_in[4];
    // d_in[5] = wedge_b (cancels in softmax), unused
    const float* wo_w    = (const float*)d_in[6];
    const float* wo_b    = (const float*)d_in[7];

    float* out   = (float*)d_out;
    float* alpha = out + (size_t)BB * NHID * LL;   // ret first, then alpha

    k1_q  <<<dim3(32, BB),        128 >>>(x, wq_w, wq_b);
    k2_ew <<<dim3(NH, BB),        1024>>>(wedge_w);
    k3_attn<<<dim3(NH, 16, BB),   256 >>>(edge, alpha);
    k4_out<<<dim3(32, BB),        128 >>>(wo_w, wo_b, out);
}

// round 4
// speedup vs baseline: 1.0349x; 1.0349x over previous
#include <cuda_runtime.h>

#define LL 1024
#define BB 4
#define NHID 128
#define NH 10
#define HD 10
#define DD 100
#define INV_SQRT_HD 0.31622776601683794f

typedef unsigned long long ull;

// Scratch (device globals: no allocation allowed)
static __device__ float q_s[BB][DD][LL];                      // q = WQ @ x (= k = v)
static __device__ float E_s[BB][NH][LL];                      // exp(s_j - gmax)
static __device__ __align__(16) float W_s[BB][NH][HD][LL];    // E * k
// att in the reference's scrambled channel layout: att_flat[b][n*LL*HD + i*HD + d]
static __device__ float att_s[BB][DD * LL];

__device__ __forceinline__ void ffma2(ull &acc, ull a, ull b) {
    asm("fma.rn.f32x2 %0, %1, %2, %0;" : "+l"(acc) : "l"(a), "l"(b));
}

// ---------------------------------------------------------------------------
// Kernel 1: q[b,c,l] = sum_h wq_w[c,h] * x[b,h,l] + wq_b[c]
// Single-stage smem, 4c x 4l register blocking. grid (32 l-tiles, B), 256 thr.
// dyn smem: xs[128][36] (18432B) + wsm[128][128] (65536B) = 83968B
// (wsm rows padded to 128 so unguarded float4 reads at c0<=124 stay in-bounds;
//  stores remain guarded by c < DD)
// ---------------------------------------------------------------------------
__global__ void __launch_bounds__(256) k1_q(const float* __restrict__ x,
                                            const float* __restrict__ wq_w,
                                            const float* __restrict__ wq_b) {
    extern __shared__ __align__(16) char smem1[];
    float (*xs)[36]   = (float(*)[36])smem1;                 // [h][l]
    float (*wsm)[128] = (float(*)[128])(smem1 + 18432);      // [h][c] (transposed, padded)

    int b = blockIdx.y, lt = blockIdx.x;
    int tid = threadIdx.x;

    // stage x tile: 128 h x 32 l
    for (int idx = tid; idx < 1024; idx += 256) {
        int h = idx >> 3, lq = idx & 7;
        float4 v = *(const float4*)&x[((size_t)(b * NHID + h) * LL) + lt * 32 + lq * 4];
        *(float4*)&xs[h][lq * 4] = v;
    }
    // stage wq_w transposed: read wq_w[c][h4*4..+3] (16B), scatter to wsm[h][c]
    for (int idx = tid; idx < 3200; idx += 256) {
        int c = idx % 100, h4 = idx / 100;
        float4 w = *(const float4*)&wq_w[c * NHID + h4 * 4];
        wsm[h4 * 4 + 0][c] = w.x;
        wsm[h4 * 4 + 1][c] = w.y;
        wsm[h4 * 4 + 2][c] = w.z;
        wsm[h4 * 4 + 3][c] = w.w;
    }
    __syncthreads();

    int lg = tid >> 5, cg = tid & 31;
    int c0 = cg * 4, l0 = lg * 4;

    float acc[4][4];
#pragma unroll
    for (int i = 0; i < 4; i++)
#pragma unroll
        for (int j = 0; j < 4; j++) acc[i][j] = 0.f;

#pragma unroll 4
    for (int h = 0; h < NHID; h++) {
        float4 wv = *(const float4*)&wsm[h][c0];
        float4 xv = *(const float4*)&xs[h][l0];
        float wa[4] = {wv.x, wv.y, wv.z, wv.w};
        float xa[4] = {xv.x, xv.y, xv.z, xv.w};
#pragma unroll
        for (int i = 0; i < 4; i++)
#pragma unroll
            for (int j = 0; j < 4; j++) acc[i][j] += wa[i] * xa[j];
    }

#pragma unroll
    for (int i = 0; i < 4; i++) {
        int c = c0 + i;
        if (c < DD) {
            float bias = __ldg(&wq_b[c]);
            float4 o = make_float4(acc[i][0] + bias, acc[i][1] + bias,
                                   acc[i][2] + bias, acc[i][3] + bias);
            *(float4*)&q_s[b][c][lt * 32 + l0] = o;
        }
    }
}

// ---------------------------------------------------------------------------
// Kernel 2: per (b,n): t[l] = inv_sqrt * sum_d q[n*hd+d][l]*wedge_w[hd+d];
// gmax = max_l t; E = exp(t-gmax); W[d][l] = E * q_d.  grid (NH,B), 1024 thr.
// ---------------------------------------------------------------------------
__global__ void __launch_bounds__(1024) k2_ew(const float* __restrict__ wedge_w) {
    int b = blockIdx.y, n = blockIdx.x;
    int l = threadIdx.x;

    float qd[HD];
    float t = 0.f;
#pragma unroll
    for (int d = 0; d < HD; d++) {
        qd[d] = q_s[b][n * HD + d][l];
        t += qd[d] * __ldg(&wedge_w[HD + d]);
    }
    t *= INV_SQRT_HD;

    __shared__ float red[32];
    float m = t;
#pragma unroll
    for (int o = 16; o; o >>= 1) m = fmaxf(m, __shfl_xor_sync(0xffffffffu, m, o));
    if ((l & 31) == 0) red[l >> 5] = m;
    __syncthreads();
    if (l < 32) {
        float mm = red[l];
#pragma unroll
        for (int o = 16; o; o >>= 1) mm = fmaxf(mm, __shfl_xor_sync(0xffffffffu, mm, o));
        if (l == 0) red[0] = mm;
    }
    __syncthreads();
    float gmax = red[0];

    float E = expf(t - gmax);
    E_s[b][n][l] = E;
#pragma unroll
    for (int d = 0; d < HD; d++) W_s[b][n][d][l] = E * qd[d];
}

// ---------------------------------------------------------------------------
// Kernel 3: per (b, n, 128-row tile). Block = 128 threads = 4 warps; each warp
// owns 32 rows. Pass 1: lane = row; all lanes sweep columns together so E/W
// shared loads are warp-broadcast (amortized over 32 rows); mask pre-packed to
// per-row bitwords in smem; accumulation uses packed fma.rn.f32x2.
// Pass 2: warp-per-row coalesced alpha writes (only __syncwarp between).
// dyn smem: E(4096) + W(40960) + bm 4*32*33*4(16896) + attst 4*32*12*4(6144)
//         = 68096B
// ---------------------------------------------------------------------------
__global__ void __launch_bounds__(128) k3_attn(const int* __restrict__ edge,
                                               float* __restrict__ alpha_out) {
    extern __shared__ __align__(16) char smem3[];
    float* E_sm = (float*)smem3;                                   // [1024]
    float (*W_sm)[LL] = (float(*)[LL])(smem3 + 4096);              // [10][1024]
    unsigned (*bm)[32][33] = (unsigned(*)[32][33])(smem3 + 45056); // [4][32][33]
    float (*attst)[32][12] = (float(*)[32][12])(smem3 + 61952);    // [4][32][12]

    int n = blockIdx.x, tile = blockIdx.y, b = blockIdx.z;
    int tid = threadIdx.x, warp = tid >> 5, lane = tid & 31;
    int rowbase = tile * 128 + warp * 32;

    // stage E/W block-wide
    for (int idx = tid; idx < LL / 4; idx += 128)
        ((float4*)E_sm)[idx] = ((const float4*)&E_s[b][n][0])[idx];
    for (int idx = tid; idx < HD * LL / 4; idx += 128)
        ((float4*)&W_sm[0][0])[idx] = ((const float4*)&W_s[b][n][0][0])[idx];

    // stage bitmask: lane builds word for cols [lane*32, lane*32+32) per row
    for (int r = 0; r < 32; ++r) {
        const int4* mrow = (const int4*)(edge + ((size_t)(b * LL + rowbase + r) * LL));
        unsigned word = 0;
#pragma unroll
        for (int k = 0; k < 8; ++k) {
            int4 m = __ldg(&mrow[lane * 8 + k]);
            unsigned w4 = (m.x ? 1u : 0u) | (m.y ? 2u : 0u) |
                          (m.z ? 4u : 0u) | (m.w ? 8u : 0u);
            word |= w4 << (4 * k);
        }
        bm[warp][r][lane] = word;
    }
    __syncthreads();

    // ---- pass 1: lane = row ----
    ull acc[11];
#pragma unroll
    for (int v = 0; v < 11; v++) acc[v] = 0ull;

    const ulonglong2* Ep = (const ulonglong2*)E_sm;

    for (int wd = 0; wd < 32; ++wd) {
        unsigned word = bm[warp][lane][wd];
#pragma unroll
        for (int g = 0; g < 8; ++g) {
            unsigned bits = (word >> (g * 4)) & 0xFu;
            int idx = wd * 8 + g;   // ulonglong2 index: covers cols [idx*4, idx*4+4)
            unsigned lo0 = (bits & 1u) ? 0x3F800000u : 0u;
            unsigned hi0 = (bits & 2u) ? 0x3F800000u : 0u;
            unsigned lo1 = (bits & 4u) ? 0x3F800000u : 0u;
            unsigned hi1 = (bits & 8u) ? 0x3F800000u : 0u;
            ull mA = (ull)lo0 | ((ull)hi0 << 32);
            ull mB = (ull)lo1 | ((ull)hi1 << 32);
            ulonglong2 e = Ep[idx];
            ffma2(acc[10], e.x, mA);
            ffma2(acc[10], e.y, mB);
#pragma unroll
            for (int d = 0; d < HD; ++d) {
                ulonglong2 w = ((const ulonglong2*)W_sm[d])[idx];
                ffma2(acc[d], w.x, mA);
                ffma2(acc[d], w.y, mB);
            }
        }
    }

    float den = __uint_as_float((unsigned)acc[10]) +
                __uint_as_float((unsigned)(acc[10] >> 32));
    float inv = 1.0f / den;
#pragma unroll
    for (int d = 0; d < HD; ++d) {
        float s = __uint_as_float((unsigned)acc[d]) +
                  __uint_as_float((unsigned)(acc[d] >> 32));
        attst[warp][lane][d] = s * inv;
    }
    attst[warp][lane][10] = inv;
    __syncwarp();

    // write att (reference's scrambled reshape): contiguous 320 floats per warp
    {
        float* attbase = &att_s[b][(size_t)n * LL * HD + (size_t)rowbase * HD];
        for (int idx = lane; idx < 32 * HD; idx += 32)
            attbase[idx] = attst[warp][idx / HD][idx % HD];
    }

    // ---- pass 2: warp-per-row alpha writes ----
    for (int r = 0; r < 32; ++r) {
        float rinv = attst[warp][r][10];
        int i = rowbase + r;
        float4* arow = (float4*)(alpha_out + ((size_t)((b * NH + n) * LL) + i) * LL);
#pragma unroll
        for (int it = 0; it < 8; ++it) {
            int c4 = it * 32 + lane;                  // float4 index; col = c4*4
            unsigned word = bm[warp][r][c4 >> 3];
            unsigned bits = (word >> ((c4 & 7) * 4)) & 0xFu;
            float4 e = ((const float4*)E_sm)[c4];
            float4 o;
            o.x = (bits & 1u) ? e.x * rinv : 0.f;
            o.y = (bits & 2u) ? e.y * rinv : 0.f;
            o.z = (bits & 4u) ? e.z * rinv : 0.f;
            o.w = (bits & 8u) ? e.w * rinv : 0.f;
            arow[c4] = o;
        }
    }
}

// ---------------------------------------------------------------------------
// Kernel 4: ret[b,o,l] = sum_c wo_w[o,c] * att_flat[b][c*LL+l] + wo_b[o]
// Single-stage smem, 4o x 4l register blocking. grid (32 l-tiles, B), 256 thr.
// dyn smem: asm_[100][36] (14400B) + wsm[100][128] (51200B) = 65600B
// ---------------------------------------------------------------------------
__global__ void __launch_bounds__(256) k4_out(const float* __restrict__ wo_w,
                                              const float* __restrict__ wo_b,
                                              float* __restrict__ out) {
    extern __shared__ __align__(16) char smem4[];
    float (*as_)[36]  = (float(*)[36])smem4;                  // [c][l]
    float (*wsm)[128] = (float(*)[128])(smem4 + 14400);       // [c][o] (transposed)

    int b = blockIdx.y, lt = blockIdx.x;
    int tid = threadIdx.x;

    // stage att tile: 100 c x 32 l
    for (int idx = tid; idx < 800; idx += 256) {
        int c = idx >> 3, lq = idx & 7;
        float4 v = *(const float4*)&att_s[b][(size_t)c * LL + lt * 32 + lq * 4];
        *(float4*)&as_[c][lq * 4] = v;
    }
    // stage wo_w transposed: read wo_w[o][c4*4..+3] (16B), scatter to wsm[c][o]
    for (int idx = tid; idx < 3200; idx += 256) {
        int o = idx & 127, c4 = idx >> 7;   // c4 in [0,25)
        float4 w = *(const float4*)&wo_w[o * DD + c4 * 4];
        wsm[c4 * 4 + 0][o] = w.x;
        wsm[c4 * 4 + 1][o] = w.y;
        wsm[c4 * 4 + 2][o] = w.z;
        wsm[c4 * 4 + 3][o] = w.w;
    }
    __syncthreads();

    int lg = tid >> 5, og = tid & 31;
    int o0 = og * 4, l0 = lg * 4;

    float acc[4][4];
#pragma unroll
    for (int i = 0; i < 4; i++)
#pragma unroll
        for (int j = 0; j < 4; j++) acc[i][j] = 0.f;

#pragma unroll 4
    for (int c = 0; c < DD; c++) {
        float4 wv = *(const float4*)&wsm[c][o0];
        float4 av = *(const float4*)&as_[c][l0];
        float wa[4] = {wv.x, wv.y, wv.z, wv.w};
        float aa[4] = {av.x, av.y, av.z, av.w};
#pragma unroll
        for (int i = 0; i < 4; i++)
#pragma unroll
            for (int j = 0; j < 4; j++) acc[i][j] += wa[i] * aa[j];
    }

#pragma unroll
    for (int i = 0; i < 4; i++) {
        int o = o0 + i;
        float bias = __ldg(&wo_b[o]);
        float4 ov = make_float4(acc[i][0] + bias, acc[i][1] + bias,
                                acc[i][2] + bias, acc[i][3] + bias);
        *(float4*)&out[((size_t)(b * NHID + o) * LL) + lt * 32 + l0] = ov;
    }
}

// ---------------------------------------------------------------------------
extern "C" void kernel_launch(void* const* d_in, const int* in_sizes, int n_in,
                              void* d_out, int out_size) {
    const float* x       = (const float*)d_in[0];
    const int*   edge    = (const int*)  d_in[1];
    const float* wq_w    = (const float*)d_in[2];
    const float* wq_b    = (const float*)d_in[3];
    const float* wedge_w = (const float*)d_in[4];
    // d_in[5] = wedge_b (cancels in softmax), unused
    const float* wo_w    = (const float*)d_in[6];
    const float* wo_b    = (const float*)d_in[7];

    float* out   = (float*)d_out;
    float* alpha = out + (size_t)BB * NHID * LL;   // ret first, then alpha

    static int attr_done = 0;
    if (!attr_done) {
        cudaFuncSetAttribute(k1_q,    cudaFuncAttributeMaxDynamicSharedMemorySize, 83968);
        cudaFuncSetAttribute(k3_attn, cudaFuncAttributeMaxDynamicSharedMemorySize, 68096);
        cudaFuncSetAttribute(k4_out,  cudaFuncAttributeMaxDynamicSharedMemorySize, 65600);
        attr_done = 1;
    }

    k1_q   <<<dim3(32, BB),      256, 83968>>>(x, wq_w, wq_b);
    k2_ew  <<<dim3(NH, BB),      1024>>>(wedge_w);
    k3_attn<<<dim3(NH, 8, BB),   128, 68096>>>(edge, alpha);
    k4_out <<<dim3(32, BB),      256, 65600>>>(wo_w, wo_b, out);
}

// round 5
// speedup vs baseline: 1.2160x; 1.1751x over previous
#include <cuda_runtime.h>

#define LL 1024
#define BB 4
#define NHID 128
#define NH 10
#define HD 10
#define DD 100
#define INV_SQRT_HD 0.31622776601683794f

typedef unsigned long long ull;

// Scratch (device globals: no allocation allowed)
static __device__ float q_s[BB][DD][LL];                      // q = WQ @ x (= k = v)
static __device__ float E_s[BB][NH][LL];                      // exp(s_j - gmax)
static __device__ __align__(16) float W_s[BB][NH][HD][LL];    // E * k
// att in the reference's scrambled channel layout: att_flat[b][n*LL*HD + i*HD + d]
static __device__ float att_s[BB][DD * LL];
// packed edge mask: bit k of word w covers col w*32+k; flat [b][row][32 words]
static __device__ __align__(16) unsigned bmg[BB * LL * 32];

__device__ __forceinline__ void ffma2(ull &acc, ull a, ull b) {
    asm("fma.rn.f32x2 %0, %1, %2, %0;" : "+l"(acc) : "l"(a), "l"(b));
}

// ---------------------------------------------------------------------------
// Kernel 0: pack edge (4M int32) -> bitmask (128K words). Coalesced + ballot.
// grid 512 x 256 threads; each thread handles 32 ints.
// ---------------------------------------------------------------------------
__global__ void __launch_bounds__(256) k0_pack(const int* __restrict__ edge) {
    unsigned t = blockIdx.x * 256 + threadIdx.x;   // 131072 threads
#pragma unroll
    for (int it = 0; it < 32; ++it) {
        unsigned g = it * 131072u + t;
        unsigned word = __ballot_sync(0xffffffffu, edge[g] != 0);
        if ((threadIdx.x & 31) == 0) bmg[g >> 5] = word;
    }
}

// ---------------------------------------------------------------------------
// Kernel 1: q[b,c,l] = sum_h wq_w[c,h] * x[b,h,l] + wq_b[c]
// Natural-layout weight smem (coalesced staging), 4c x 4l register blocking.
// grid (32 l-tiles, B), 256 thr.
// dyn smem: xs[128][36] (18432B) + wsm[100][129] (51600B) = 70032B
// ---------------------------------------------------------------------------
__global__ void __launch_bounds__(256) k1_q(const float* __restrict__ x,
                                            const float* __restrict__ wq_w,
                                            const float* __restrict__ wq_b) {
    extern __shared__ __align__(16) char smem1[];
    float (*xs)[36]   = (float(*)[36])smem1;                 // [h][l]
    float (*wsm)[129] = (float(*)[129])(smem1 + 18432);      // [c][h] natural, odd pad

    int b = blockIdx.y, lt = blockIdx.x;
    int tid = threadIdx.x;

    // stage x tile: 128 h x 32 l (coalesced, 128B rows)
    for (int idx = tid; idx < 1024; idx += 256) {
        int h = idx >> 3, lq = idx & 7;
        float4 v = *(const float4*)&x[((size_t)(b * NHID + h) * LL) + lt * 32 + lq * 4];
        *(float4*)&xs[h][lq * 4] = v;
    }
    // stage wq_w natural layout: flat coalesced float4 reads, scalar stores
    for (int f = tid; f < 3200; f += 256) {
        float4 w = ((const float4*)wq_w)[f];
        int c = f >> 5, h = (f & 31) * 4;     // wq_w row = 128 floats = 32 float4
        wsm[c][h + 0] = w.x;
        wsm[c][h + 1] = w.y;
        wsm[c][h + 2] = w.z;
        wsm[c][h + 3] = w.w;
    }
    __syncthreads();

    int lg = tid >> 5, cg = tid & 31;
    int c0 = cg * 4, l0 = lg * 4;
    int c0c = (c0 > 96) ? 96 : c0;            // clamp so loads stay in-bounds

    float acc[4][4];
#pragma unroll
    for (int i = 0; i < 4; i++)
#pragma unroll
        for (int j = 0; j < 4; j++) acc[i][j] = 0.f;

#pragma unroll 4
    for (int h = 0; h < NHID; h++) {
        float wa[4];
#pragma unroll
        for (int i = 0; i < 4; i++) wa[i] = wsm[c0c + i][h];
        float4 xv = *(const float4*)&xs[h][l0];
        float xa[4] = {xv.x, xv.y, xv.z, xv.w};
#pragma unroll
        for (int i = 0; i < 4; i++)
#pragma unroll
            for (int j = 0; j < 4; j++) acc[i][j] += wa[i] * xa[j];
    }

#pragma unroll
    for (int i = 0; i < 4; i++) {
        int c = c0 + i;                        // guard with UNclamped c
        if (c < DD) {
            float bias = __ldg(&wq_b[c]);
            float4 o = make_float4(acc[i][0] + bias, acc[i][1] + bias,
                                   acc[i][2] + bias, acc[i][3] + bias);
            *(float4*)&q_s[b][c][lt * 32 + l0] = o;
        }
    }
}

// ---------------------------------------------------------------------------
// Kernel 2: per (b,n): t[l] = inv_sqrt * sum_d q[n*hd+d][l]*wedge_w[hd+d];
// gmax = max_l t; E = exp(t-gmax); W[d][l] = E * q_d.  grid (NH,B), 1024 thr.
// ---------------------------------------------------------------------------
__global__ void __launch_bounds__(1024) k2_ew(const float* __restrict__ wedge_w) {
    int b = blockIdx.y, n = blockIdx.x;
    int l = threadIdx.x;

    float qd[HD];
    float t = 0.f;
#pragma unroll
    for (int d = 0; d < HD; d++) {
        qd[d] = q_s[b][n * HD + d][l];
        t += qd[d] * __ldg(&wedge_w[HD + d]);
    }
    t *= INV_SQRT_HD;

    __shared__ float red[32];
    float m = t;
#pragma unroll
    for (int o = 16; o; o >>= 1) m = fmaxf(m, __shfl_xor_sync(0xffffffffu, m, o));
    if ((l & 31) == 0) red[l >> 5] = m;
    __syncthreads();
    if (l < 32) {
        float mm = red[l];
#pragma unroll
        for (int o = 16; o; o >>= 1) mm = fmaxf(mm, __shfl_xor_sync(0xffffffffu, mm, o));
        if (l == 0) red[0] = mm;
    }
    __syncthreads();
    float gmax = red[0];

    float E = expf(t - gmax);
    E_s[b][n][l] = E;
#pragma unroll
    for (int d = 0; d < HD; d++) W_s[b][n][d][l] = E * qd[d];
}

// ---------------------------------------------------------------------------
// Kernel 3: per (b, n, 256-row tile). 256 threads = 8 warps; each warp owns 32
// rows. Pass 1: lane = row; E/W shared loads are warp-broadcast; mask comes
// from the PACKED global bitmask, staged coalescedly into smem; accumulation
// uses packed fma.rn.f32x2. Pass 2: warp-per-row coalesced alpha writes.
// dyn smem: E(4096)+W(40960)+bm 256*33*4(33792)+attst 256*13*4(13312)=92160B
// ---------------------------------------------------------------------------
__global__ void __launch_bounds__(256) k3_attn(float* __restrict__ alpha_out) {
    extern __shared__ __align__(16) char smem3[];
    float* E_sm = (float*)smem3;                                   // [1024]
    float (*W_sm)[LL] = (float(*)[LL])(smem3 + 4096);              // [10][1024]
    unsigned (*bm)[33] = (unsigned(*)[33])(smem3 + 45056);         // [256][33]
    float (*attst)[13] = (float(*)[13])(smem3 + 78848);            // [256][13]

    int n = blockIdx.x, tile = blockIdx.y, b = blockIdx.z;
    int tid = threadIdx.x, warp = tid >> 5, lane = tid & 31;
    int rowbase = tile * 256;

    // stage E/W block-wide (coalesced float4)
    for (int idx = tid; idx < LL / 4; idx += 256)
        ((float4*)E_sm)[idx] = ((const float4*)&E_s[b][n][0])[idx];
    for (int idx = tid; idx < HD * LL / 4; idx += 256)
        ((float4*)&W_sm[0][0])[idx] = ((const float4*)&W_s[b][n][0][0])[idx];

    // stage packed mask: 256 rows x 32 words, int4 coalesced from bmg
    {
        const int4* src = (const int4*)(bmg + (size_t)(b * LL + rowbase) * 32);
        for (int idx = tid; idx < 2048; idx += 256) {
            int4 v = src[idx];
            int row = idx >> 3, w0 = (idx & 7) * 4;
            bm[row][w0 + 0] = (unsigned)v.x;
            bm[row][w0 + 1] = (unsigned)v.y;
            bm[row][w0 + 2] = (unsigned)v.z;
            bm[row][w0 + 3] = (unsigned)v.w;
        }
    }
    __syncthreads();

    int myrow = warp * 32 + lane;   // this lane's row within the 256-row tile

    // ---- pass 1: lane = row ----
    ull acc[11];
#pragma unroll
    for (int v = 0; v < 11; v++) acc[v] = 0ull;

    const ulonglong2* Ep = (const ulonglong2*)E_sm;

    for (int wd = 0; wd < 32; ++wd) {
        unsigned word = bm[myrow][wd];
#pragma unroll
        for (int g = 0; g < 8; ++g) {
            unsigned bits = (word >> (g * 4)) & 0xFu;
            int idx = wd * 8 + g;   // ulonglong2 index: covers cols [idx*4, idx*4+4)
            unsigned lo0 = (bits & 1u) ? 0x3F800000u : 0u;
            unsigned hi0 = (bits & 2u) ? 0x3F800000u : 0u;
            unsigned lo1 = (bits & 4u) ? 0x3F800000u : 0u;
            unsigned hi1 = (bits & 8u) ? 0x3F800000u : 0u;
            ull mA = (ull)lo0 | ((ull)hi0 << 32);
            ull mB = (ull)lo1 | ((ull)hi1 << 32);
            ulonglong2 e = Ep[idx];
            ffma2(acc[10], e.x, mA);
            ffma2(acc[10], e.y, mB);
#pragma unroll
            for (int d = 0; d < HD; ++d) {
                ulonglong2 w = ((const ulonglong2*)W_sm[d])[idx];
                ffma2(acc[d], w.x, mA);
                ffma2(acc[d], w.y, mB);
            }
        }
    }

    float den = __uint_as_float((unsigned)acc[10]) +
                __uint_as_float((unsigned)(acc[10] >> 32));
    float inv = 1.0f / den;
#pragma unroll
    for (int d = 0; d < HD; ++d) {
        float s = __uint_as_float((unsigned)acc[d]) +
                  __uint_as_float((unsigned)(acc[d] >> 32));
        attst[myrow][d] = s * inv;
    }
    attst[myrow][10] = inv;
    __syncwarp();

    // write att (reference's scrambled reshape): 320 contiguous floats per warp
    {
        float* attbase = &att_s[b][(size_t)n * LL * HD + (size_t)(rowbase + warp * 32) * HD];
        for (int idx = lane; idx < 32 * HD; idx += 32)
            attbase[idx] = attst[warp * 32 + idx / HD][idx % HD];
    }

    // ---- pass 2: warp-per-row alpha writes ----
    for (int r = 0; r < 32; ++r) {
        int row256 = warp * 32 + r;
        float rinv = attst[row256][10];
        int i = rowbase + row256;
        float4* arow = (float4*)(alpha_out + ((size_t)((b * NH + n) * LL) + i) * LL);
#pragma unroll
        for (int it = 0; it < 8; ++it) {
            int c4 = it * 32 + lane;                  // float4 index; col = c4*4
            unsigned word = bm[row256][c4 >> 3];
            unsigned bits = (word >> ((c4 & 7) * 4)) & 0xFu;
            float4 e = ((const float4*)E_sm)[c4];
            float4 o;
            o.x = (bits & 1u) ? e.x * rinv : 0.f;
            o.y = (bits & 2u) ? e.y * rinv : 0.f;
            o.z = (bits & 4u) ? e.z * rinv : 0.f;
            o.w = (bits & 8u) ? e.w * rinv : 0.f;
            arow[c4] = o;
        }
    }
}

// ---------------------------------------------------------------------------
// Kernel 4: ret[b,o,l] = sum_c wo_w[o,c] * att_flat[b][c*LL+l] + wo_b[o]
// Split o into 2 halves of 64; natural-layout weight smem (coalesced staging).
// grid (32 l-tiles, 2 o-halves, B), 128 thr.
// dyn smem: as_[100][36] (14400B) + wsm[64][101] (25856B) = 40256B
// ---------------------------------------------------------------------------
__global__ void __launch_bounds__(128) k4_out(const float* __restrict__ wo_w,
                                              const float* __restrict__ wo_b,
                                              float* __restrict__ out) {
    extern __shared__ __align__(16) char smem4[];
    float (*as_)[36]  = (float(*)[36])smem4;                  // [c][l]
    float (*wsm)[101] = (float(*)[101])(smem4 + 14400);       // [o_local][c] natural

    int lt = blockIdx.x, oh = blockIdx.y, b = blockIdx.z;
    int tid = threadIdx.x;

    // stage att tile: 100 c x 32 l (coalesced)
    for (int idx = tid; idx < 800; idx += 128) {
        int c = idx >> 3, lq = idx & 7;
        float4 v = *(const float4*)&att_s[b][(size_t)c * LL + lt * 32 + lq * 4];
        *(float4*)&as_[c][lq * 4] = v;
    }
    // stage wo_w half: 64 rows x 100 c = 6400 floats = 1600 float4, coalesced
    {
        const float4* src = (const float4*)(wo_w + (size_t)oh * 64 * DD);
        for (int f = tid; f < 1600; f += 128) {
            float4 w = src[f];
            int p = f * 4;
#pragma unroll
            for (int k = 0; k < 4; k++) {
                int pk = p + k;
                int ol = pk / DD, c = pk % DD;
                float v = (k == 0) ? w.x : (k == 1) ? w.y : (k == 2) ? w.z : w.w;
                wsm[ol][c] = v;
            }
        }
    }
    __syncthreads();

    int lg = tid >> 4, og = tid & 15;
    int ol0 = og * 4, l0 = lg * 4;

    float acc[4][4];
#pragma unroll
    for (int i = 0; i < 4; i++)
#pragma unroll
        for (int j = 0; j < 4; j++) acc[i][j] = 0.f;

#pragma unroll 4
    for (int c = 0; c < DD; c++) {
        float wa[4];
#pragma unroll
        for (int i = 0; i < 4; i++) wa[i] = wsm[ol0 + i][c];
        float4 av = *(const float4*)&as_[c][l0];
        float aa[4] = {av.x, av.y, av.z, av.w};
#pragma unroll
        for (int i = 0; i < 4; i++)
#pragma unroll
            for (int j = 0; j < 4; j++) acc[i][j] += wa[i] * aa[j];
    }

#pragma unroll
    for (int i = 0; i < 4; i++) {
        int o = oh * 64 + ol0 + i;
        float bias = __ldg(&wo_b[o]);
        float4 ov = make_float4(acc[i][0] + bias, acc[i][1] + bias,
                                acc[i][2] + bias, acc[i][3] + bias);
        *(float4*)&out[((size_t)(b * NHID + o) * LL) + lt * 32 + l0] = ov;
    }
}

// ---------------------------------------------------------------------------
extern "C" void kernel_launch(void* const* d_in, const int* in_sizes, int n_in,
                              void* d_out, int out_size) {
    const float* x       = (const float*)d_in[0];
    const int*   edge    = (const int*)  d_in[1];
    const float* wq_w    = (const float*)d_in[2];
    const float* wq_b    = (const float*)d_in[3];
    const float* wedge_w = (const float*)d_in[4];
    // d_in[5] = wedge_b (cancels in softmax), unused
    const float* wo_w    = (const float*)d_in[6];
    const float* wo_b    = (const float*)d_in[7];

    float* out   = (float*)d_out;
    float* alpha = out + (size_t)BB * NHID * LL;   // ret first, then alpha

    static int attr_done = 0;
    if (!attr_done) {
        cudaFuncSetAttribute(k1_q,    cudaFuncAttributeMaxDynamicSharedMemorySize, 70032);
        cudaFuncSetAttribute(k3_attn, cudaFuncAttributeMaxDynamicSharedMemorySize, 92160);
        cudaFuncSetAttribute(k4_out,  cudaFuncAttributeMaxDynamicSharedMemorySize, 40256);
        attr_done = 1;
    }

    k0_pack<<<512, 256>>>(edge);
    k1_q   <<<dim3(32, BB),      256, 70032>>>(x, wq_w, wq_b);
    k2_ew  <<<dim3(NH, BB),      1024>>>(wedge_w);
    k3_attn<<<dim3(NH, 4, BB),   256, 92160>>>(alpha);
    k4_out <<<dim3(32, 2, BB),   128, 40256>>>(wo_w, wo_b, out);
}

// round 6
// speedup vs baseline: 1.2720x; 1.0461x over previous
#include <cuda_runtime.h>

#define LL 1024
#define BB 4
#define NHID 128
#define NH 10
#define HD 10
#define DD 100
#define INV_SQRT_HD 0.31622776601683794f

typedef unsigned long long ull;

// Scratch (device globals: no allocation allowed)
static __device__ float q_s[BB][DD][LL];                      // q = WQ @ x (= k = v)
static __device__ __align__(16) float E_s[BB][NH][LL];        // exp(s_j - gmax)
static __device__ __align__(16) float W_s[BB][NH][HD][LL];    // E * k
static __device__ float inv_s[BB][NH][LL];                    // 1/denom per row
// att in the reference's scrambled channel layout: att_flat[b][n*LL*HD + i*HD + d]
static __device__ float att_s[BB][DD * LL];
// packed edge mask: bit k of word w covers col w*32+k; flat [b][row][32 words]
static __device__ __align__(16) unsigned bmg[BB * LL * 32];

__device__ __forceinline__ void ffma2(ull &acc, ull a, ull b) {
    asm("fma.rn.f32x2 %0, %1, %2, %0;" : "+l"(acc) : "l"(a), "l"(b));
}

// ---------------------------------------------------------------------------
// Kernel 0: pack edge (4M int32) -> bitmask (128K words). Coalesced + ballot.
// ---------------------------------------------------------------------------
__global__ void __launch_bounds__(256) k0_pack(const int* __restrict__ edge) {
    unsigned t = blockIdx.x * 256 + threadIdx.x;   // 131072 threads
#pragma unroll
    for (int it = 0; it < 32; ++it) {
        unsigned g = it * 131072u + t;
        unsigned word = __ballot_sync(0xffffffffu, edge[g] != 0);
        if ((threadIdx.x & 31) == 0) bmg[g >> 5] = word;
    }
}

// ---------------------------------------------------------------------------
// Kernel 1: q[b,c,l] = sum_h wq_w[c,h] * x[b,h,l] + wq_b[c]
// dyn smem: xs[128][36] (18432B) + wsm[100][129] (51600B) = 70032B
// ---------------------------------------------------------------------------
__global__ void __launch_bounds__(256) k1_q(const float* __restrict__ x,
                                            const float* __restrict__ wq_w,
                                            const float* __restrict__ wq_b) {
    extern __shared__ __align__(16) char smem1[];
    float (*xs)[36]   = (float(*)[36])smem1;                 // [h][l]
    float (*wsm)[129] = (float(*)[129])(smem1 + 18432);      // [c][h] natural, odd pad

    int b = blockIdx.y, lt = blockIdx.x;
    int tid = threadIdx.x;

    for (int idx = tid; idx < 1024; idx += 256) {
        int h = idx >> 3, lq = idx & 7;
        float4 v = *(const float4*)&x[((size_t)(b * NHID + h) * LL) + lt * 32 + lq * 4];
        *(float4*)&xs[h][lq * 4] = v;
    }
    for (int f = tid; f < 3200; f += 256) {
        float4 w = ((const float4*)wq_w)[f];
        int c = f >> 5, h = (f & 31) * 4;
        wsm[c][h + 0] = w.x;
        wsm[c][h + 1] = w.y;
        wsm[c][h + 2] = w.z;
        wsm[c][h + 3] = w.w;
    }
    __syncthreads();

    int lg = tid >> 5, cg = tid & 31;
    int c0 = cg * 4, l0 = lg * 4;
    int c0c = (c0 > 96) ? 96 : c0;

    float acc[4][4];
#pragma unroll
    for (int i = 0; i < 4; i++)
#pragma unroll
        for (int j = 0; j < 4; j++) acc[i][j] = 0.f;

#pragma unroll 4
    for (int h = 0; h < NHID; h++) {
        float wa[4];
#pragma unroll
        for (int i = 0; i < 4; i++) wa[i] = wsm[c0c + i][h];
        float4 xv = *(const float4*)&xs[h][l0];
        float xa[4] = {xv.x, xv.y, xv.z, xv.w};
#pragma unroll
        for (int i = 0; i < 4; i++)
#pragma unroll
            for (int j = 0; j < 4; j++) acc[i][j] += wa[i] * xa[j];
    }

#pragma unroll
    for (int i = 0; i < 4; i++) {
        int c = c0 + i;
        if (c < DD) {
            float bias = __ldg(&wq_b[c]);
            float4 o = make_float4(acc[i][0] + bias, acc[i][1] + bias,
                                   acc[i][2] + bias, acc[i][3] + bias);
            *(float4*)&q_s[b][c][lt * 32 + l0] = o;
        }
    }
}

// ---------------------------------------------------------------------------
// Kernel 2: E/W computation. grid (NH,B), 1024 thr.
// ---------------------------------------------------------------------------
__global__ void __launch_bounds__(1024) k2_ew(const float* __restrict__ wedge_w) {
    int b = blockIdx.y, n = blockIdx.x;
    int l = threadIdx.x;

    float qd[HD];
    float t = 0.f;
#pragma unroll
    for (int d = 0; d < HD; d++) {
        qd[d] = q_s[b][n * HD + d][l];
        t += qd[d] * __ldg(&wedge_w[HD + d]);
    }
    t *= INV_SQRT_HD;

    __shared__ float red[32];
    float m = t;
#pragma unroll
    for (int o = 16; o; o >>= 1) m = fmaxf(m, __shfl_xor_sync(0xffffffffu, m, o));
    if ((l & 31) == 0) red[l >> 5] = m;
    __syncthreads();
    if (l < 32) {
        float mm = red[l];
#pragma unroll
        for (int o = 16; o; o >>= 1) mm = fmaxf(mm, __shfl_xor_sync(0xffffffffu, mm, o));
        if (l == 0) red[0] = mm;
    }
    __syncthreads();
    float gmax = red[0];

    float E = expf(t - gmax);
    E_s[b][n][l] = E;
#pragma unroll
    for (int d = 0; d < HD; d++) W_s[b][n][d][l] = E * qd[d];
}

// ---------------------------------------------------------------------------
// Kernel 3a: att + denom. Per (b, n, 128-row tile). 256 threads = 8 warps.
// Warps 0-3: lane = row (128 rows), columns [0,512). Warps 4-7: same rows,
// columns [512,1024). Partial sums combined via smem; writes att_s + inv_s.
// dyn smem: E(4096)+W(40960)+bm 128*33*4(16896)+part 2*128*12*4(12288)=74240B
// ---------------------------------------------------------------------------
__global__ void __launch_bounds__(256) k3a_att(void) {
    extern __shared__ __align__(16) char smem3[];
    float* E_sm = (float*)smem3;                                   // [1024]
    float (*W_sm)[LL] = (float(*)[LL])(smem3 + 4096);              // [10][1024]
    unsigned (*bm)[33] = (unsigned(*)[33])(smem3 + 45056);         // [128][33]
    float (*part)[128][12] = (float(*)[128][12])(smem3 + 61952);   // [2][128][12]

    int n = blockIdx.x, tile = blockIdx.y, b = blockIdx.z;
    int tid = threadIdx.x, warp = tid >> 5, lane = tid & 31;
    int rowbase = tile * 128;

    for (int idx = tid; idx < LL / 4; idx += 256)
        ((float4*)E_sm)[idx] = ((const float4*)&E_s[b][n][0])[idx];
    for (int idx = tid; idx < HD * LL / 4; idx += 256)
        ((float4*)&W_sm[0][0])[idx] = ((const float4*)&W_s[b][n][0][0])[idx];
    {
        const int4* src = (const int4*)(bmg + (size_t)(b * LL + rowbase) * 32);
        for (int idx = tid; idx < 1024; idx += 256) {
            int4 v = src[idx];
            int row = idx >> 3, w0 = (idx & 7) * 4;
            bm[row][w0 + 0] = (unsigned)v.x;
            bm[row][w0 + 1] = (unsigned)v.y;
            bm[row][w0 + 2] = (unsigned)v.z;
            bm[row][w0 + 3] = (unsigned)v.w;
        }
    }
    __syncthreads();

    int half = warp >> 2;                 // 0: cols [0,512), 1: cols [512,1024)
    int myrow = (warp & 3) * 32 + lane;   // row within 128-row tile

    ull acc[11];
#pragma unroll
    for (int v = 0; v < 11; v++) acc[v] = 0ull;

    const ulonglong2* Ep = (const ulonglong2*)E_sm;

    for (int wd = half * 16; wd < half * 16 + 16; ++wd) {
        unsigned word = bm[myrow][wd];
#pragma unroll
        for (int g = 0; g < 8; ++g) {
            unsigned bits = (word >> (g * 4)) & 0xFu;
            int idx = wd * 8 + g;   // ulonglong2 index: cols [idx*4, idx*4+4)
            unsigned lo0 = (bits & 1u) ? 0x3F800000u : 0u;
            unsigned hi0 = (bits & 2u) ? 0x3F800000u : 0u;
            unsigned lo1 = (bits & 4u) ? 0x3F800000u : 0u;
            unsigned hi1 = (bits & 8u) ? 0x3F800000u : 0u;
            ull mA = (ull)lo0 | ((ull)hi0 << 32);
            ull mB = (ull)lo1 | ((ull)hi1 << 32);
            ulonglong2 e = Ep[idx];
            ffma2(acc[10], e.x, mA);
            ffma2(acc[10], e.y, mB);
#pragma unroll
            for (int d = 0; d < HD; ++d) {
                ulonglong2 w = ((const ulonglong2*)W_sm[d])[idx];
                ffma2(acc[d], w.x, mA);
                ffma2(acc[d], w.y, mB);
            }
        }
    }

#pragma unroll
    for (int v = 0; v < 11; ++v) {
        float s = __uint_as_float((unsigned)acc[v]) +
                  __uint_as_float((unsigned)(acc[v] >> 32));
        part[half][myrow][v] = s;
    }
    __syncthreads();

    if (tid < 128) {
        int row = tid;
        float den = part[0][row][10] + part[1][row][10];
        float inv = 1.0f / den;
        float* attbase = &att_s[b][(size_t)n * LL * HD + (size_t)(rowbase + row) * HD];
#pragma unroll
        for (int d = 0; d < HD; ++d)
            attbase[d] = (part[0][row][d] + part[1][row][d]) * inv;
        inv_s[b][n][rowbase + row] = inv;
    }
}

// ---------------------------------------------------------------------------
// Kernel 3b: alpha streaming write. grid (LL/4, NH, B), 1024 threads.
// Block handles 4 rows of (b,n); thread = one float4 of one row.
// E/bm/inv all L2-resident (160KB/512KB/160KB). Pure write-BW kernel.
// ---------------------------------------------------------------------------
__global__ void __launch_bounds__(1024) k3b_alpha(float* __restrict__ alpha_out) {
    int rg = blockIdx.x, n = blockIdx.y, b = blockIdx.z;
    int rl = threadIdx.x >> 8;          // 0..3
    int c4 = threadIdx.x & 255;         // float4 index; cols [c4*4, c4*4+4)
    int row = rg * 4 + rl;

    float4 e = __ldg(&((const float4*)&E_s[b][n][0])[c4]);
    unsigned word = __ldg(&bmg[(size_t)(b * LL + row) * 32 + (c4 >> 3)]);
    unsigned bits = (word >> ((c4 & 7) * 4)) & 0xFu;
    float inv = __ldg(&inv_s[b][n][row]);

    float4 o;
    o.x = (bits & 1u) ? e.x * inv : 0.f;
    o.y = (bits & 2u) ? e.y * inv : 0.f;
    o.z = (bits & 4u) ? e.z * inv : 0.f;
    o.w = (bits & 8u) ? e.w * inv : 0.f;

    ((float4*)(alpha_out + ((size_t)((b * NH + n) * LL) + row) * LL))[c4] = o;
}

// ---------------------------------------------------------------------------
// Kernel 4: ret[b,o,l] = sum_c wo_w[o,c] * att_flat[b][c*LL+l] + wo_b[o]
// dyn smem: as_[100][36] (14400B) + wsm[64][101] (25856B) = 40256B
// ---------------------------------------------------------------------------
__global__ void __launch_bounds__(128) k4_out(const float* __restrict__ wo_w,
                                              const float* __restrict__ wo_b,
                                              float* __restrict__ out) {
    extern __shared__ __align__(16) char smem4[];
    float (*as_)[36]  = (float(*)[36])smem4;                  // [c][l]
    float (*wsm)[101] = (float(*)[101])(smem4 + 14400);       // [o_local][c] natural

    int lt = blockIdx.x, oh = blockIdx.y, b = blockIdx.z;
    int tid = threadIdx.x;

    for (int idx = tid; idx < 800; idx += 128) {
        int c = idx >> 3, lq = idx & 7;
        float4 v = *(const float4*)&att_s[b][(size_t)c * LL + lt * 32 + lq * 4];
        *(float4*)&as_[c][lq * 4] = v;
    }
    {
        const float4* src = (const float4*)(wo_w + (size_t)oh * 64 * DD);
        for (int f = tid; f < 1600; f += 128) {
            float4 w = src[f];
            int p = f * 4;
#pragma unroll
            for (int k = 0; k < 4; k++) {
                int pk = p + k;
                int ol = pk / DD, c = pk % DD;
                float v = (k == 0) ? w.x : (k == 1) ? w.y : (k == 2) ? w.z : w.w;
                wsm[ol][c] = v;
            }
        }
    }
    __syncthreads();

    int lg = tid >> 4, og = tid & 15;
    int ol0 = og * 4, l0 = lg * 4;

    float acc[4][4];
#pragma unroll
    for (int i = 0; i < 4; i++)
#pragma unroll
        for (int j = 0; j < 4; j++) acc[i][j] = 0.f;

#pragma unroll 4
    for (int c = 0; c < DD; c++) {
        float wa[4];
#pragma unroll
        for (int i = 0; i < 4; i++) wa[i] = wsm[ol0 + i][c];
        float4 av = *(const float4*)&as_[c][l0];
        float aa[4] = {av.x, av.y, av.z, av.w};
#pragma unroll
        for (int i = 0; i < 4; i++)
#pragma unroll
            for (int j = 0; j < 4; j++) acc[i][j] += wa[i] * aa[j];
    }

#pragma unroll
    for (int i = 0; i < 4; i++) {
        int o = oh * 64 + ol0 + i;
        float bias = __ldg(&wo_b[o]);
        float4 ov = make_float4(acc[i][0] + bias, acc[i][1] + bias,
                                acc[i][2] + bias, acc[i][3] + bias);
        *(float4*)&out[((size_t)(b * NHID + o) * LL) + lt * 32 + l0] = ov;
    }
}

// ---------------------------------------------------------------------------
extern "C" void kernel_launch(void* const* d_in, const int* in_sizes, int n_in,
                              void* d_out, int out_size) {
    const float* x       = (const float*)d_in[0];
    const int*   edge    = (const int*)  d_in[1];
    const float* wq_w    = (const float*)d_in[2];
    const float* wq_b    = (const float*)d_in[3];
    const float* wedge_w = (const float*)d_in[4];
    // d_in[5] = wedge_b (cancels in softmax), unused
    const float* wo_w    = (const float*)d_in[6];
    const float* wo_b    = (const float*)d_in[7];

    float* out   = (float*)d_out;
    float* alpha = out + (size_t)BB * NHID * LL;   // ret first, then alpha

    static int attr_done = 0;
    if (!attr_done) {
        cudaFuncSetAttribute(k1_q,    cudaFuncAttributeMaxDynamicSharedMemorySize, 70032);
        cudaFuncSetAttribute(k3a_att, cudaFuncAttributeMaxDynamicSharedMemorySize, 74240);
        cudaFuncSetAttribute(k4_out,  cudaFuncAttributeMaxDynamicSharedMemorySize, 40256);
        attr_done = 1;
    }

    k0_pack <<<512, 256>>>(edge);
    k1_q    <<<dim3(32, BB),        256, 70032>>>(x, wq_w, wq_b);
    k2_ew   <<<dim3(NH, BB),        1024>>>(wedge_w);
    k3a_att <<<dim3(NH, 8, BB),     256, 74240>>>();
    k4_out  <<<dim3(32, 2, BB),     128, 40256>>>(wo_w, wo_b, out);
    k3b_alpha<<<dim3(LL / 4, NH, BB), 1024>>>(alpha);
}

// round 7
// speedup vs baseline: 1.3739x; 1.0801x over previous
#include <cuda_runtime.h>

#define LL 1024
#define BB 4
#define NHID 128
#define NH 10
#define HD 10
#define DD 100
#define INV_SQRT_HD 0.31622776601683794f

typedef unsigned long long ull;

// Scratch (device globals: no allocation allowed)
static __device__ float qp_s[2][BB][DD][LL];                  // q partials (h-split)
static __device__ __align__(16) float E_s[BB][NH][LL];        // exp(s_j - gmax)
static __device__ __align__(16) float W_s[BB][NH][HD][LL];    // E * k
static __device__ float inv_s[BB][NH][LL];                    // 1/denom per row
// att in the reference's scrambled channel layout: att_flat[b][n*LL*HD + i*HD + d]
static __device__ float att_s[BB][DD * LL];
// packed edge mask: bit k of word w covers col w*32+k; flat [b][row][32 words]
static __device__ __align__(16) unsigned bmg[BB * LL * 32];

__device__ __forceinline__ void ffma2(ull &acc, ull a, ull b) {
    asm("fma.rn.f32x2 %0, %1, %2, %0;" : "+l"(acc) : "l"(a), "l"(b));
}
__device__ __forceinline__ float pairsum(ull a) {
    return __uint_as_float((unsigned)a) + __uint_as_float((unsigned)(a >> 32));
}

// ---------------------------------------------------------------------------
// Kernel 0: pack edge (4M int32) -> bitmask (128K words). Coalesced + ballot.
// ---------------------------------------------------------------------------
__global__ void __launch_bounds__(256) k0_pack(const int* __restrict__ edge) {
    unsigned t = blockIdx.x * 256 + threadIdx.x;   // 131072 threads
#pragma unroll
    for (int it = 0; it < 32; ++it) {
        unsigned g = it * 131072u + t;
        unsigned word = __ballot_sync(0xffffffffu, edge[g] != 0);
        if ((threadIdx.x & 31) == 0) bmg[g >> 5] = word;
    }
}

// ---------------------------------------------------------------------------
// Kernel 1: q partials. qp[hh][b][c][l] = sum_{h in hh-half} wq_w[c,h]*x[b,h,l]
// k-split over h doubles block count (latency hiding). Bias added in k2.
// grid (32 l-tiles, 2 h-halves, B), 256 thr.
// dyn smem: xs[64][36] (9216B) + wsm[100][65] (26000B) = 35216B
// ---------------------------------------------------------------------------
__global__ void __launch_bounds__(256) k1_q(const float* __restrict__ x,
                                            const float* __restrict__ wq_w) {
    extern __shared__ __align__(16) char smem1[];
    float (*xs)[36]  = (float(*)[36])smem1;                  // [h][l]
    float (*wsm)[65] = (float(*)[65])(smem1 + 9216);         // [c][h] natural, odd pad

    int lt = blockIdx.x, hh = blockIdx.y, b = blockIdx.z;
    int tid = threadIdx.x;

    // stage x tile: 64 h x 32 l (coalesced)
    for (int idx = tid; idx < 512; idx += 256) {
        int h = idx >> 3, lq = idx & 7;
        float4 v = *(const float4*)&x[((size_t)(b * NHID + hh * 64 + h) * LL) + lt * 32 + lq * 4];
        *(float4*)&xs[h][lq * 4] = v;
    }
    // stage wq_w half: 100 c x 64 h = 1600 float4, coalesced-ish rows
    for (int f = tid; f < 1600; f += 256) {
        int c = f >> 4, h4 = f & 15;
        float4 w = ((const float4*)wq_w)[c * 32 + hh * 16 + h4];
        wsm[c][h4 * 4 + 0] = w.x;
        wsm[c][h4 * 4 + 1] = w.y;
        wsm[c][h4 * 4 + 2] = w.z;
        wsm[c][h4 * 4 + 3] = w.w;
    }
    __syncthreads();

    int lg = tid >> 5, cg = tid & 31;
    int c0 = cg * 4, l0 = lg * 4;
    int c0c = (c0 > 96) ? 96 : c0;

    float acc[4][4];
#pragma unroll
    for (int i = 0; i < 4; i++)
#pragma unroll
        for (int j = 0; j < 4; j++) acc[i][j] = 0.f;

#pragma unroll 4
    for (int h = 0; h < 64; h++) {
        float wa[4];
#pragma unroll
        for (int i = 0; i < 4; i++) wa[i] = wsm[c0c + i][h];
        float4 xv = *(const float4*)&xs[h][l0];
        float xa[4] = {xv.x, xv.y, xv.z, xv.w};
#pragma unroll
        for (int i = 0; i < 4; i++)
#pragma unroll
            for (int j = 0; j < 4; j++) acc[i][j] += wa[i] * xa[j];
    }

#pragma unroll
    for (int i = 0; i < 4; i++) {
        int c = c0 + i;
        if (c < DD) {
            float4 o = make_float4(acc[i][0], acc[i][1], acc[i][2], acc[i][3]);
            *(float4*)&qp_s[hh][b][c][lt * 32 + l0] = o;
        }
    }
}

// ---------------------------------------------------------------------------
// Kernel 2: E/W computation (sums q halves + bias). grid (NH,B), 1024 thr.
// ---------------------------------------------------------------------------
__global__ void __launch_bounds__(1024) k2_ew(const float* __restrict__ wedge_w,
                                              const float* __restrict__ wq_b) {
    int b = blockIdx.y, n = blockIdx.x;
    int l = threadIdx.x;

    float qd[HD];
    float t = 0.f;
#pragma unroll
    for (int d = 0; d < HD; d++) {
        int c = n * HD + d;
        qd[d] = qp_s[0][b][c][l] + qp_s[1][b][c][l] + __ldg(&wq_b[c]);
        t += qd[d] * __ldg(&wedge_w[HD + d]);
    }
    t *= INV_SQRT_HD;

    __shared__ float red[32];
    float m = t;
#pragma unroll
    for (int o = 16; o; o >>= 1) m = fmaxf(m, __shfl_xor_sync(0xffffffffu, m, o));
    if ((l & 31) == 0) red[l >> 5] = m;
    __syncthreads();
    if (l < 32) {
        float mm = red[l];
#pragma unroll
        for (int o = 16; o; o >>= 1) mm = fmaxf(mm, __shfl_xor_sync(0xffffffffu, mm, o));
        if (l == 0) red[0] = mm;
    }
    __syncthreads();
    float gmax = red[0];

    float E = expf(t - gmax);
    E_s[b][n][l] = E;
#pragma unroll
    for (int d = 0; d < HD; d++) W_s[b][n][d][l] = E * qd[d];
}

// ---------------------------------------------------------------------------
// Kernel 3a: att + denom. Per (b, n, 128-row tile). 256 threads = 8 warps.
// Warp w: col-quarter q=w>>1 (256 cols), row-half h=w&1; lane owns TWO rows
// (r0 = h*64+lane, r1 = r0+32) so every uniform E/W LDS.128 broadcast is
// amortized over 2 rows (halves smem traffic vs 1 row/lane). Deterministic
// 4-way partial combine in smem; writes att_s + inv_s.
// dyn smem: E(4096)+W(40960)+bm 128*33*4(16896)+part 4*128*12*4(24576)=86528B
// ---------------------------------------------------------------------------
__global__ void __launch_bounds__(256) k3a_att(void) {
    extern __shared__ __align__(16) char smem3[];
    float* E_sm = (float*)smem3;                                   // [1024]
    float (*W_sm)[LL] = (float(*)[LL])(smem3 + 4096);              // [10][1024]
    unsigned (*bm)[33] = (unsigned(*)[33])(smem3 + 45056);         // [128][33]
    float (*part)[128][12] = (float(*)[128][12])(smem3 + 61952);   // [4][128][12]

    int n = blockIdx.x, tile = blockIdx.y, b = blockIdx.z;
    int tid = threadIdx.x, warp = tid >> 5, lane = tid & 31;
    int rowbase = tile * 128;

    for (int idx = tid; idx < LL / 4; idx += 256)
        ((float4*)E_sm)[idx] = ((const float4*)&E_s[b][n][0])[idx];
    for (int idx = tid; idx < HD * LL / 4; idx += 256)
        ((float4*)&W_sm[0][0])[idx] = ((const float4*)&W_s[b][n][0][0])[idx];
    {
        const int4* src = (const int4*)(bmg + (size_t)(b * LL + rowbase) * 32);
        for (int idx = tid; idx < 1024; idx += 256) {
            int4 v = src[idx];
            int row = idx >> 3, w0 = (idx & 7) * 4;
            bm[row][w0 + 0] = (unsigned)v.x;
            bm[row][w0 + 1] = (unsigned)v.y;
            bm[row][w0 + 2] = (unsigned)v.z;
            bm[row][w0 + 3] = (unsigned)v.w;
        }
    }
    __syncthreads();

    int cq = warp >> 1;                 // col quarter: words [cq*8, cq*8+8)
    int rh = warp & 1;                  // row half
    int r0 = rh * 64 + lane, r1 = r0 + 32;

    ull accA[11], accB[11];
#pragma unroll
    for (int v = 0; v < 11; v++) { accA[v] = 0ull; accB[v] = 0ull; }

    const ulonglong2* Ep = (const ulonglong2*)E_sm;

    for (int wd = cq * 8; wd < cq * 8 + 8; ++wd) {
        unsigned wordA = bm[r0][wd];
        unsigned wordB = bm[r1][wd];
#pragma unroll
        for (int g = 0; g < 8; ++g) {
            int idx = wd * 8 + g;       // ulonglong2 index: cols [idx*4, idx*4+4)
            unsigned bA = (wordA >> (g * 4)) & 0xFu;
            unsigned bB = (wordB >> (g * 4)) & 0xFu;
            ull mA0 = (ull)((bA & 1u) ? 0x3F800000u : 0u) |
                      ((ull)((bA & 2u) ? 0x3F800000u : 0u) << 32);
            ull mA1 = (ull)((bA & 4u) ? 0x3F800000u : 0u) |
                      ((ull)((bA & 8u) ? 0x3F800000u : 0u) << 32);
            ull mB0 = (ull)((bB & 1u) ? 0x3F800000u : 0u) |
                      ((ull)((bB & 2u) ? 0x3F800000u : 0u) << 32);
            ull mB1 = (ull)((bB & 4u) ? 0x3F800000u : 0u) |
                      ((ull)((bB & 8u) ? 0x3F800000u : 0u) << 32);
            ulonglong2 e = Ep[idx];
            ffma2(accA[10], e.x, mA0);
            ffma2(accA[10], e.y, mA1);
            ffma2(accB[10], e.x, mB0);
            ffma2(accB[10], e.y, mB1);
#pragma unroll
            for (int d = 0; d < HD; ++d) {
                ulonglong2 w = ((const ulonglong2*)W_sm[d])[idx];
                ffma2(accA[d], w.x, mA0);
                ffma2(accA[d], w.y, mA1);
                ffma2(accB[d], w.x, mB0);
                ffma2(accB[d], w.y, mB1);
            }
        }
    }

#pragma unroll
    for (int v = 0; v < 11; ++v) {
        part[cq][r0][v] = pairsum(accA[v]);
        part[cq][r1][v] = pairsum(accB[v]);
    }
    __syncthreads();

    if (tid < 128) {
        int row = tid;
        float s[11];
#pragma unroll
        for (int v = 0; v < 11; ++v)
            s[v] = (part[0][row][v] + part[1][row][v]) +
                   (part[2][row][v] + part[3][row][v]);
        float inv = 1.0f / s[10];
        float* attbase = &att_s[b][(size_t)n * LL * HD + (size_t)(rowbase + row) * HD];
#pragma unroll
        for (int d = 0; d < HD; ++d)
            attbase[d] = s[d] * inv;
        inv_s[b][n][rowbase + row] = inv;
    }
}

// ---------------------------------------------------------------------------
// Kernel 3b: alpha streaming write. grid (LL/4, NH, B), 1024 threads.
// Pure write-BW kernel; E/bm/inv all L2-resident.
// ---------------------------------------------------------------------------
__global__ void __launch_bounds__(1024) k3b_alpha(float* __restrict__ alpha_out) {
    int rg = blockIdx.x, n = blockIdx.y, b = blockIdx.z;
    int rl = threadIdx.x >> 8;          // 0..3
    int c4 = threadIdx.x & 255;         // float4 index; cols [c4*4, c4*4+4)
    int row = rg * 4 + rl;

    float4 e = __ldg(&((const float4*)&E_s[b][n][0])[c4]);
    unsigned word = __ldg(&bmg[(size_t)(b * LL + row) * 32 + (c4 >> 3)]);
    unsigned bits = (word >> ((c4 & 7) * 4)) & 0xFu;
    float inv = __ldg(&inv_s[b][n][row]);

    float4 o;
    o.x = (bits & 1u) ? e.x * inv : 0.f;
    o.y = (bits & 2u) ? e.y * inv : 0.f;
    o.z = (bits & 4u) ? e.z * inv : 0.f;
    o.w = (bits & 8u) ? e.w * inv : 0.f;

    ((float4*)(alpha_out + ((size_t)((b * NH + n) * LL) + row) * LL))[c4] = o;
}

// ---------------------------------------------------------------------------
// Kernel 4: ret[b,o,l] = sum_c wo_w[o,c] * att_flat[b][c*LL+l] + wo_b[o]
// dyn smem: as_[100][36] (14400B) + wsm[64][101] (25856B) = 40256B
// ---------------------------------------------------------------------------
__global__ void __launch_bounds__(128) k4_out(const float* __restrict__ wo_w,
                                              const float* __restrict__ wo_b,
                                              float* __restrict__ out) {
    extern __shared__ __align__(16) char smem4[];
    float (*as_)[36]  = (float(*)[36])smem4;                  // [c][l]
    float (*wsm)[101] = (float(*)[101])(smem4 + 14400);       // [o_local][c] natural

    int lt = blockIdx.x, oh = blockIdx.y, b = blockIdx.z;
    int tid = threadIdx.x;

    for (int idx = tid; idx < 800; idx += 128) {
        int c = idx >> 3, lq = idx & 7;
        float4 v = *(const float4*)&att_s[b][(size_t)c * LL + lt * 32 + lq * 4];
        *(float4*)&as_[c][lq * 4] = v;
    }
    {
        const float4* src = (const float4*)(wo_w + (size_t)oh * 64 * DD);
        for (int f = tid; f < 1600; f += 128) {
            float4 w = src[f];
            int p = f * 4;
#pragma unroll
            for (int k = 0; k < 4; k++) {
                int pk = p + k;
                int ol = pk / DD, c = pk % DD;
                float v = (k == 0) ? w.x : (k == 1) ? w.y : (k == 2) ? w.z : w.w;
                wsm[ol][c] = v;
            }
        }
    }
    __syncthreads();

    int lg = tid >> 4, og = tid & 15;
    int ol0 = og * 4, l0 = lg * 4;

    float acc[4][4];
#pragma unroll
    for (int i = 0; i < 4; i++)
#pragma unroll
        for (int j = 0; j < 4; j++) acc[i][j] = 0.f;

#pragma unroll 4
    for (int c = 0; c < DD; c++) {
        float wa[4];
#pragma unroll
        for (int i = 0; i < 4; i++) wa[i] = wsm[ol0 + i][c];
        float4 av = *(const float4*)&as_[c][l0];
        float aa[4] = {av.x, av.y, av.z, av.w};
#pragma unroll
        for (int i = 0; i < 4; i++)
#pragma unroll
            for (int j = 0; j < 4; j++) acc[i][j] += wa[i] * aa[j];
    }

#pragma unroll
    for (int i = 0; i < 4; i++) {
        int o = oh * 64 + ol0 + i;
        float bias = __ldg(&wo_b[o]);
        float4 ov = make_float4(acc[i][0] + bias, acc[i][1] + bias,
                                acc[i][2] + bias, acc[i][3] + bias);
        *(float4*)&out[((size_t)(b * NHID + o) * LL) + lt * 32 + l0] = ov;
    }
}

// ---------------------------------------------------------------------------
extern "C" void kernel_launch(void* const* d_in, const int* in_sizes, int n_in,
                              void* d_out, int out_size) {
    const float* x       = (const float*)d_in[0];
    const int*   edge    = (const int*)  d_in[1];
    const float* wq_w    = (const float*)d_in[2];
    const float* wq_b    = (const float*)d_in[3];
    const float* wedge_w = (const float*)d_in[4];
    // d_in[5] = wedge_b (cancels in softmax), unused
    const float* wo_w    = (const float*)d_in[6];
    const float* wo_b    = (const float*)d_in[7];

    float* out   = (float*)d_out;
    float* alpha = out + (size_t)BB * NHID * LL;   // ret first, then alpha

    static int attr_done = 0;
    if (!attr_done) {
        cudaFuncSetAttribute(k1_q,    cudaFuncAttributeMaxDynamicSharedMemorySize, 35216);
        cudaFuncSetAttribute(k3a_att, cudaFuncAttributeMaxDynamicSharedMemorySize, 86528);
        cudaFuncSetAttribute(k4_out,  cudaFuncAttributeMaxDynamicSharedMemorySize, 40256);
        attr_done = 1;
    }

    k0_pack <<<512, 256>>>(edge);
    k1_q    <<<dim3(32, 2, BB),     256, 35216>>>(x, wq_w);
    k2_ew   <<<dim3(NH, BB),        1024>>>(wedge_w, wq_b);
    k3a_att <<<dim3(NH, 8, BB),     256, 86528>>>();
    k4_out  <<<dim3(32, 2, BB),     128, 40256>>>(wo_w, wo_b, out);
    k3b_alpha<<<dim3(LL / 4, NH, BB), 1024>>>(alpha);
}